// round 10
// baseline (speedup 1.0000x reference)
#include <cuda_runtime.h>
#include <cuda_fp16.h>
#include <math.h>
#include <stdint.h>

#define B_TOK 16384
#define DIM   1024          // K
#define HID   2048
#define NE    4
#define NC    3
#define NTOT  (NE * HID)    // 8192 rows of folded W1 (N dimension)

#define BM 128
#define BN 128
#define BK 64               // 64 halfs = 128B per row (full SW128 atom)
#define KITERS (DIM / BK)   // 16
#define STAGES 4
#define ASTG 16384          // A stage bytes: 128*64*2
#define STG  (2 * ASTG)     // 32 KB / stage
#define DYN_SMEM (STAGES * STG)  // 128 KB

// ---- device scratch (allocation-free) ----
__device__ __align__(1024) __half g_normed_h[(size_t)B_TOK * DIM];  // 32 MB
__device__ __align__(1024) __half g_w1h[(size_t)NTOT * DIM];        // 16 MB (K-major, g-folded)
__device__ __align__(1024) float  g_b1f[NTOT];                      // b1 + lnb@w1
__device__ __align__(1024) float  g_gate[B_TOK * NE];

// ============================ PTX helpers (sm_80-safe only) ============================
__device__ __forceinline__ uint32_t smem_u32(const void* p) {
    uint32_t a;
    asm("{ .reg .u64 t; cvta.to.shared.u64 t, %1; cvt.u32.u64 %0, t; }" : "=r"(a) : "l"(p));
    return a;
}
__device__ __forceinline__ void cp16(uint32_t sa, const void* g) {
    asm volatile("cp.async.cg.shared.global [%0], [%1], 16;" :: "r"(sa), "l"(g) : "memory");
}
#define CP_COMMIT() asm volatile("cp.async.commit_group;" ::: "memory")
#define CP_WAIT(n)  asm volatile("cp.async.wait_group %0;" :: "n"(n) : "memory")

#define LDSM4(r, a) \
    asm volatile("ldmatrix.sync.aligned.m8n8.x4.shared.b16 {%0,%1,%2,%3}, [%4];" \
        : "=r"((r)[0]), "=r"((r)[1]), "=r"((r)[2]), "=r"((r)[3]) : "r"(a))

#define MMA16816(d, a, b) \
    asm volatile("mma.sync.aligned.m16n8k16.row.col.f32.f16.f16.f32 " \
        "{%0,%1,%2,%3}, {%4,%5,%6,%7}, {%8,%9}, {%0,%1,%2,%3};" \
        : "+f"((d)[0]), "+f"((d)[1]), "+f"((d)[2]), "+f"((d)[3]) \
        : "r"((a)[0]), "r"((a)[1]), "r"((a)[2]), "r"((a)[3]), "r"((b)[0]), "r"((b)[1]))

__device__ __forceinline__ float gelu_exact(float v) {
    return 0.5f * v * (1.0f + erff(v * 0.70710678118654752f));
}

// ============== K0: LayerNorm + gate softmax + out bias init ==============
__global__ __launch_bounds__(256) void ln_gate_kernel(
    const float* __restrict__ x,
    const float* __restrict__ gln_g, const float* __restrict__ gln_b,
    const float* __restrict__ gate_w, const float* __restrict__ gate_b,
    const float* __restrict__ ex_b2, float* __restrict__ out)
{
    const int row = blockIdx.x, t = threadIdx.x;
    const int lane = t & 31, warp = t >> 5;

    const float4 xv = *(const float4*)(x + (size_t)row * DIM + t * 4);
    float s  = xv.x + xv.y + xv.z + xv.w;
    float ss = xv.x * xv.x + xv.y * xv.y + xv.z * xv.z + xv.w * xv.w;
#pragma unroll
    for (int o = 16; o; o >>= 1) {
        s  += __shfl_xor_sync(0xffffffffu, s, o);
        ss += __shfl_xor_sync(0xffffffffu, ss, o);
    }
    __shared__ float rs[8], rss[8];
    if (lane == 0) { rs[warp] = s; rss[warp] = ss; }
    __syncthreads();
    s = 0.f; ss = 0.f;
#pragma unroll
    for (int w = 0; w < 8; w++) { s += rs[w]; ss += rss[w]; }
    const float mu = s * (1.0f / DIM);
    const float var = ss * (1.0f / DIM) - mu * mu;
    const float rstd = rsqrtf(var + 1e-5f);

    float4 nv;
    nv.x = (xv.x - mu) * rstd; nv.y = (xv.y - mu) * rstd;
    nv.z = (xv.z - mu) * rstd; nv.w = (xv.w - mu) * rstd;
    __half2* np = (__half2*)(g_normed_h + (size_t)row * DIM + t * 4);
    np[0] = __floats2half2_rn(nv.x, nv.y);
    np[1] = __floats2half2_rn(nv.z, nv.w);

    const int d0 = t * 4;
    const float4 gg = *(const float4*)(gln_g + d0);
    const float4 gb = *(const float4*)(gln_b + d0);
    float y0 = fmaf(nv.x, gg.x, gb.x), y1 = fmaf(nv.y, gg.y, gb.y);
    float y2 = fmaf(nv.z, gg.z, gb.z), y3 = fmaf(nv.w, gg.w, gb.w);
    float l0 = 0.f, l1 = 0.f, l2 = 0.f, l3 = 0.f;
    float4 w;
    w = *(const float4*)(gate_w + (size_t)(d0 + 0) * NE);
    l0 += y0 * w.x; l1 += y0 * w.y; l2 += y0 * w.z; l3 += y0 * w.w;
    w = *(const float4*)(gate_w + (size_t)(d0 + 1) * NE);
    l0 += y1 * w.x; l1 += y1 * w.y; l2 += y1 * w.z; l3 += y1 * w.w;
    w = *(const float4*)(gate_w + (size_t)(d0 + 2) * NE);
    l0 += y2 * w.x; l1 += y2 * w.y; l2 += y2 * w.z; l3 += y2 * w.w;
    w = *(const float4*)(gate_w + (size_t)(d0 + 3) * NE);
    l0 += y3 * w.x; l1 += y3 * w.y; l2 += y3 * w.z; l3 += y3 * w.w;
#pragma unroll
    for (int o = 16; o; o >>= 1) {
        l0 += __shfl_xor_sync(0xffffffffu, l0, o);
        l1 += __shfl_xor_sync(0xffffffffu, l1, o);
        l2 += __shfl_xor_sync(0xffffffffu, l2, o);
        l3 += __shfl_xor_sync(0xffffffffu, l3, o);
    }
    __shared__ float lr[8][4];
    if (lane == 0) { lr[warp][0] = l0; lr[warp][1] = l1; lr[warp][2] = l2; lr[warp][3] = l3; }
    __syncthreads();
    if (t == 0) {
        float L[NE];
#pragma unroll
        for (int e = 0; e < NE; e++) {
            float a = gate_b[e];
#pragma unroll
            for (int wg = 0; wg < 8; wg++) a += lr[wg][e];
            L[e] = a;
        }
        float m = L[0];
#pragma unroll
        for (int e = 1; e < NE; e++) m = fmaxf(m, L[e]);
        float sum = 0.f, ew[NE];
#pragma unroll
        for (int e = 0; e < NE; e++) { ew[e] = expf(L[e] - m); sum += ew[e]; }
        const float inv = 1.0f / sum;
#pragma unroll
        for (int e = 0; e < NE; e++) g_gate[row * NE + e] = ew[e] * inv;
#pragma unroll
        for (int c = 0; c < NC; c++) {
            float a = 0.f;
#pragma unroll
            for (int e = 0; e < NE; e++) a += ew[e] * inv * ex_b2[e * NC + c];
            out[row * NC + c] = a;
        }
    }
}

// ===== K1: fold ln gain into w1, transpose to [e*H+h][d] K-major, cast fp16 =====
__global__ __launch_bounds__(256) void fold_w1_kernel(
    const float* __restrict__ w1, const float* __restrict__ lng)
{
    __shared__ float tile[32][33];
    const int tx = threadIdx.x, ty = threadIdx.y;
    const int h0 = blockIdx.x * 32, d0 = blockIdx.y * 32, e = blockIdx.z;
#pragma unroll
    for (int i = 0; i < 4; i++) {
        const int d = d0 + ty + i * 8;
        tile[ty + i * 8][tx] = w1[((size_t)e * DIM + d) * HID + h0 + tx] * lng[e * DIM + d];
    }
    __syncthreads();
#pragma unroll
    for (int i = 0; i < 4; i++) {
        const int h = h0 + ty + i * 8;
        g_w1h[((size_t)e * HID + h) * DIM + d0 + tx] = __float2half_rn(tile[tx][ty + i * 8]);
    }
}

// ===== K2: b1f[e][h] = b1[e][h] + sum_d lnb[e][d] * w1[e][d][h] =====
__global__ __launch_bounds__(256) void fold_b1_kernel(
    const float* __restrict__ w1, const float* __restrict__ lnb,
    const float* __restrict__ b1)
{
    const int e = blockIdx.y;
    const int h = blockIdx.x * 256 + threadIdx.x;
    float acc = b1[e * HID + h];
    const float* wp = w1 + (size_t)e * DIM * HID + h;
    const float* bp = lnb + e * DIM;
#pragma unroll 4
    for (int d = 0; d < DIM; d++) acc += bp[d] * wp[(size_t)d * HID];
    g_b1f[e * HID + h] = acc;
}

// ============== K3: mma.sync fp16 GEMM, register-double-buffered fragments ==============
// 1 CTA/SM (regs ~150), 4 smem stages. LDSM for ks+1 issues ahead of the MMAs of ks,
// so the tensor pipe never waits on smem latency; stage-advance sync sits under the
// draining MMA queue at ks==3.
__global__ __launch_bounds__(256, 1) void gemm_kernel(
    const float* __restrict__ ex_w2, float* __restrict__ out)
{
    extern __shared__ __align__(1024) char smem[];
    __shared__ float sred[BM * NC];
    const uint32_t sb = smem_u32(smem);
    const int t = threadIdx.x;
    const int warp = t >> 5, lane = t & 31;
    const int row0 = blockIdx.x * BM;
    const int n0 = blockIdx.y * BN;
    const int wm = warp >> 2;      // 0..1 -> 64-row band
    const int wn = warp & 3;       // 0..3 -> 32-col band

    float acc[4][4][4];
#pragma unroll
    for (int mi = 0; mi < 4; mi++)
#pragma unroll
        for (int nf = 0; nf < 4; nf++)
#pragma unroll
            for (int q = 0; q < 4; q++) acc[mi][nf][q] = 0.f;

    // ---- loader: thread t handles chunks i = t + 256j (j=0..3) for A and B ----
    const int lrow = t >> 3, lc = t & 7;
    const uint32_t ldst = lrow * 128 + ((lc ^ (lrow & 7)) * 16);   // + j*4096
    const char* gA = (const char*)(g_normed_h + (size_t)(row0 + lrow) * DIM) + lc * 16;
    const char* gB = (const char*)(g_w1h + (size_t)(n0 + lrow) * DIM) + lc * 16;

    // ---- ldmatrix base offsets per ks ----
    uint32_t aoff0[4], boff0[4];
    {
        const int arow = wm * 64 + (lane & 15);
        const int brow = wn * 32 + (lane & 15);
        const int hi = lane >> 4;
#pragma unroll
        for (int ks = 0; ks < 4; ks++) {
            const int c = ks * 2 + hi;
            aoff0[ks] = arow * 128 + ((c ^ (arow & 7)) * 16);
            boff0[ks] = ASTG + brow * 128 + ((c ^ (brow & 7)) * 16);
        }
    }

    // ---- fragment ping-pong buffers ----
    uint32_t fa[2][4][4], fb[2][4][2];

    // ---- prologue: fill STAGES-1 stages ----
#pragma unroll
    for (int s = 0; s < STAGES - 1; s++) {
        const uint32_t sbase = sb + s * STG;
#pragma unroll
        for (int j = 0; j < 4; j++) {
            cp16(sbase + ldst + j * 4096, gA + j * 65536);
            cp16(sbase + ASTG + ldst + j * 4096, gB + j * 65536);
        }
        gA += 128; gB += 128;
        CP_COMMIT();
    }
    CP_WAIT(2);
    __syncthreads();

    // preload fragments (stage 0, ks 0) into buffer 0
    {
        const uint32_t ab = sb + aoff0[0];
        const uint32_t bb = sb + boff0[0];
#pragma unroll
        for (int mi = 0; mi < 4; mi++) LDSM4(fa[0][mi], ab + mi * 2048);
#pragma unroll
        for (int g = 0; g < 2; g++) {
            uint32_t r[4];
            LDSM4(r, bb + g * 2048);
            fb[0][2 * g][0] = r[0];     fb[0][2 * g][1] = r[2];
            fb[0][2 * g + 1][0] = r[1]; fb[0][2 * g + 1][1] = r[3];
        }
    }

    for (int it = 0; it < KITERS; it++) {
        // producer: k-chunk it+3 into stage (it+3)&3
        if (it + STAGES - 1 < KITERS) {
            const uint32_t sbase = sb + ((it + STAGES - 1) & 3) * STG;
#pragma unroll
            for (int j = 0; j < 4; j++) {
                cp16(sbase + ldst + j * 4096, gA + j * 65536);
                cp16(sbase + ASTG + ldst + j * 4096, gB + j * 65536);
            }
            gA += 128; gB += 128;
        }
        CP_COMMIT();

        const uint32_t sS = sb + (it & 3) * STG;
#pragma unroll
        for (int ks = 0; ks < 4; ks++) {
            const int cur = ks & 1, nxt = cur ^ 1;
            // prefetch next fragment set BEFORE this step's MMAs
            if (ks < 3) {
                const uint32_t ab = sS + aoff0[ks + 1];
                const uint32_t bb = sS + boff0[ks + 1];
#pragma unroll
                for (int mi = 0; mi < 4; mi++) LDSM4(fa[nxt][mi], ab + mi * 2048);
#pragma unroll
                for (int g = 0; g < 2; g++) {
                    uint32_t r[4];
                    LDSM4(r, bb + g * 2048);
                    fb[nxt][2 * g][0] = r[0];     fb[nxt][2 * g][1] = r[2];
                    fb[nxt][2 * g + 1][0] = r[1]; fb[nxt][2 * g + 1][1] = r[3];
                }
            } else if (it + 1 < KITERS) {
                CP_WAIT(2);                 // stage it+1 complete
                __syncthreads();            // MMA queue drains under the barrier
                const uint32_t sN = sb + ((it + 1) & 3) * STG;
                const uint32_t ab = sN + aoff0[0];
                const uint32_t bb = sN + boff0[0];
#pragma unroll
                for (int mi = 0; mi < 4; mi++) LDSM4(fa[nxt][mi], ab + mi * 2048);
#pragma unroll
                for (int g = 0; g < 2; g++) {
                    uint32_t r[4];
                    LDSM4(r, bb + g * 2048);
                    fb[nxt][2 * g][0] = r[0];     fb[nxt][2 * g][1] = r[2];
                    fb[nxt][2 * g + 1][0] = r[1]; fb[nxt][2 * g + 1][1] = r[3];
                }
            }
#pragma unroll
            for (int mi = 0; mi < 4; mi++)
#pragma unroll
                for (int nf = 0; nf < 4; nf++)
                    MMA16816(acc[mi][nf], fa[cur][mi], fb[cur][nf]);
        }
    }
    CP_WAIT(0);

    // ---- epilogue: +b1f, exact GELU, x w2 (H->3), smem row-reduce, gated atomics ----
    const int e = blockIdx.y >> 4;   // expert = n0 / HID
    for (int i = t; i < BM * NC; i += 256) sred[i] = 0.f;
    __syncthreads();

#pragma unroll
    for (int mi = 0; mi < 4; mi++) {
        float s00 = 0.f, s01 = 0.f, s02 = 0.f;
        float s10 = 0.f, s11 = 0.f, s12 = 0.f;
#pragma unroll
        for (int nf = 0; nf < 4; nf++) {
            const int n = n0 + wn * 32 + nf * 8 + (lane & 3) * 2;
            const float b1a = __ldg(&g_b1f[n]), b1b = __ldg(&g_b1f[n + 1]);
            const float wa0 = __ldg(&ex_w2[n * 3 + 0]);
            const float wa1 = __ldg(&ex_w2[n * 3 + 1]);
            const float wa2 = __ldg(&ex_w2[n * 3 + 2]);
            const float wb0 = __ldg(&ex_w2[n * 3 + 3]);
            const float wb1 = __ldg(&ex_w2[n * 3 + 4]);
            const float wb2 = __ldg(&ex_w2[n * 3 + 5]);
            const float v00 = gelu_exact(acc[mi][nf][0] + b1a);
            const float v01 = gelu_exact(acc[mi][nf][1] + b1b);
            const float v10 = gelu_exact(acc[mi][nf][2] + b1a);
            const float v11 = gelu_exact(acc[mi][nf][3] + b1b);
            s00 += v00 * wa0 + v01 * wb0;
            s01 += v00 * wa1 + v01 * wb1;
            s02 += v00 * wa2 + v01 * wb2;
            s10 += v10 * wa0 + v11 * wb0;
            s11 += v10 * wa1 + v11 * wb1;
            s12 += v10 * wa2 + v11 * wb2;
        }
#pragma unroll
        for (int o = 2; o; o >>= 1) {
            s00 += __shfl_xor_sync(0xffffffffu, s00, o);
            s01 += __shfl_xor_sync(0xffffffffu, s01, o);
            s02 += __shfl_xor_sync(0xffffffffu, s02, o);
            s10 += __shfl_xor_sync(0xffffffffu, s10, o);
            s11 += __shfl_xor_sync(0xffffffffu, s11, o);
            s12 += __shfl_xor_sync(0xffffffffu, s12, o);
        }
        if ((lane & 3) == 0) {
            const int rl = wm * 64 + mi * 16 + (lane >> 2);
            atomicAdd(&sred[rl * NC + 0], s00);
            atomicAdd(&sred[rl * NC + 1], s01);
            atomicAdd(&sred[rl * NC + 2], s02);
            atomicAdd(&sred[(rl + 8) * NC + 0], s10);
            atomicAdd(&sred[(rl + 8) * NC + 1], s11);
            atomicAdd(&sred[(rl + 8) * NC + 2], s12);
        }
    }
    __syncthreads();

    if (t < BM) {
        const int row = row0 + t;
        const float gw = g_gate[row * NE + e];
        atomicAdd(&out[row * NC + 0], gw * sred[t * NC + 0]);
        atomicAdd(&out[row * NC + 1], gw * sred[t * NC + 1]);
        atomicAdd(&out[row * NC + 2], gw * sred[t * NC + 2]);
    }
}

// ==================================================================================
extern "C" void kernel_launch(void* const* d_in, const int* in_sizes, int n_in,
                              void* d_out, int out_size)
{
    const float* x       = (const float*)d_in[0];
    const float* gln_g   = (const float*)d_in[1];
    const float* gln_b   = (const float*)d_in[2];
    const float* gate_w  = (const float*)d_in[3];
    const float* gate_b  = (const float*)d_in[4];
    const float* ex_ln_g = (const float*)d_in[5];
    const float* ex_ln_b = (const float*)d_in[6];
    const float* ex_w1   = (const float*)d_in[7];
    const float* ex_b1   = (const float*)d_in[8];
    const float* ex_w2   = (const float*)d_in[9];
    const float* ex_b2   = (const float*)d_in[10];
    float* out = (float*)d_out;

    cudaFuncSetAttribute(gemm_kernel, cudaFuncAttributeMaxDynamicSharedMemorySize, DYN_SMEM);

    ln_gate_kernel<<<B_TOK, 256>>>(x, gln_g, gln_b, gate_w, gate_b, ex_b2, out);
    fold_w1_kernel<<<dim3(HID / 32, DIM / 32, NE), dim3(32, 8)>>>(ex_w1, ex_ln_g);
    fold_b1_kernel<<<dim3(HID / 256, NE), 256>>>(ex_w1, ex_ln_b, ex_b1);
    gemm_kernel<<<dim3(B_TOK / BM, NTOT / BN), 256, DYN_SMEM>>>(ex_w2, out);
}

// round 11
// speedup vs baseline: 1.0985x; 1.0985x over previous
#include <cuda_runtime.h>
#include <cuda_fp16.h>
#include <math.h>
#include <stdint.h>

#define B_TOK 16384
#define DIM   1024          // K
#define HID   2048
#define NE    4
#define NC    3
#define NTOT  (NE * HID)    // 8192 rows of folded W1 (N dimension)

#define BM 128
#define BN 64
#define BK 64               // 64 halfs = 128B per row
#define KITERS (DIM / BK)   // 16
#define STAGES 3
#define ASTG 16384          // A stage: 128*64*2
#define BSTG 8192           // B stage: 64*64*2
#define STG  (ASTG + BSTG)  // 24 KB / stage
#define SRED_OFF (STAGES * STG)              // 73728
#define DYN_SMEM (SRED_OFF + BM * NC * 4)    // 75264 (~73.5 KB) -> 3 CTA/SM

// ---- device scratch (allocation-free) ----
__device__ __align__(1024) __half g_normed_h[(size_t)B_TOK * DIM];  // 32 MB
__device__ __align__(1024) __half g_w1h[(size_t)NTOT * DIM];        // 16 MB (K-major, g-folded)
__device__ __align__(1024) float  g_b1f[NTOT];                      // b1 + lnb@w1
__device__ __align__(1024) float  g_gate[B_TOK * NE];

// ============================ PTX helpers (sm_80-safe only) ============================
__device__ __forceinline__ uint32_t smem_u32(const void* p) {
    uint32_t a;
    asm("{ .reg .u64 t; cvta.to.shared.u64 t, %1; cvt.u32.u64 %0, t; }" : "=r"(a) : "l"(p));
    return a;
}
__device__ __forceinline__ void cp16(uint32_t sa, const void* g) {
    asm volatile("cp.async.cg.shared.global [%0], [%1], 16;" :: "r"(sa), "l"(g) : "memory");
}
#define CP_COMMIT() asm volatile("cp.async.commit_group;" ::: "memory")
#define CP_WAIT(n)  asm volatile("cp.async.wait_group %0;" :: "n"(n) : "memory")

#define LDSM4(r, a) \
    asm volatile("ldmatrix.sync.aligned.m8n8.x4.shared.b16 {%0,%1,%2,%3}, [%4];" \
        : "=r"((r)[0]), "=r"((r)[1]), "=r"((r)[2]), "=r"((r)[3]) : "r"(a))

#define MMA16816(d, a, b) \
    asm volatile("mma.sync.aligned.m16n8k16.row.col.f32.f16.f16.f32 " \
        "{%0,%1,%2,%3}, {%4,%5,%6,%7}, {%8,%9}, {%0,%1,%2,%3};" \
        : "+f"((d)[0]), "+f"((d)[1]), "+f"((d)[2]), "+f"((d)[3]) \
        : "r"((a)[0]), "r"((a)[1]), "r"((a)[2]), "r"((a)[3]), "r"((b)[0]), "r"((b)[1]))

__device__ __forceinline__ float gelu_exact(float v) {
    return 0.5f * v * (1.0f + erff(v * 0.70710678118654752f));
}

// ============== K0: LayerNorm + gate softmax + out bias init ==============
__global__ __launch_bounds__(256) void ln_gate_kernel(
    const float* __restrict__ x,
    const float* __restrict__ gln_g, const float* __restrict__ gln_b,
    const float* __restrict__ gate_w, const float* __restrict__ gate_b,
    const float* __restrict__ ex_b2, float* __restrict__ out)
{
    const int row = blockIdx.x, t = threadIdx.x;
    const int lane = t & 31, warp = t >> 5;

    const float4 xv = *(const float4*)(x + (size_t)row * DIM + t * 4);
    float s  = xv.x + xv.y + xv.z + xv.w;
    float ss = xv.x * xv.x + xv.y * xv.y + xv.z * xv.z + xv.w * xv.w;
#pragma unroll
    for (int o = 16; o; o >>= 1) {
        s  += __shfl_xor_sync(0xffffffffu, s, o);
        ss += __shfl_xor_sync(0xffffffffu, ss, o);
    }
    __shared__ float rs[8], rss[8];
    if (lane == 0) { rs[warp] = s; rss[warp] = ss; }
    __syncthreads();
    s = 0.f; ss = 0.f;
#pragma unroll
    for (int w = 0; w < 8; w++) { s += rs[w]; ss += rss[w]; }
    const float mu = s * (1.0f / DIM);
    const float var = ss * (1.0f / DIM) - mu * mu;
    const float rstd = rsqrtf(var + 1e-5f);

    float4 nv;
    nv.x = (xv.x - mu) * rstd; nv.y = (xv.y - mu) * rstd;
    nv.z = (xv.z - mu) * rstd; nv.w = (xv.w - mu) * rstd;
    __half2* np = (__half2*)(g_normed_h + (size_t)row * DIM + t * 4);
    np[0] = __floats2half2_rn(nv.x, nv.y);
    np[1] = __floats2half2_rn(nv.z, nv.w);

    const int d0 = t * 4;
    const float4 gg = *(const float4*)(gln_g + d0);
    const float4 gb = *(const float4*)(gln_b + d0);
    float y0 = fmaf(nv.x, gg.x, gb.x), y1 = fmaf(nv.y, gg.y, gb.y);
    float y2 = fmaf(nv.z, gg.z, gb.z), y3 = fmaf(nv.w, gg.w, gb.w);
    float l0 = 0.f, l1 = 0.f, l2 = 0.f, l3 = 0.f;
    float4 w;
    w = *(const float4*)(gate_w + (size_t)(d0 + 0) * NE);
    l0 += y0 * w.x; l1 += y0 * w.y; l2 += y0 * w.z; l3 += y0 * w.w;
    w = *(const float4*)(gate_w + (size_t)(d0 + 1) * NE);
    l0 += y1 * w.x; l1 += y1 * w.y; l2 += y1 * w.z; l3 += y1 * w.w;
    w = *(const float4*)(gate_w + (size_t)(d0 + 2) * NE);
    l0 += y2 * w.x; l1 += y2 * w.y; l2 += y2 * w.z; l3 += y2 * w.w;
    w = *(const float4*)(gate_w + (size_t)(d0 + 3) * NE);
    l0 += y3 * w.x; l1 += y3 * w.y; l2 += y3 * w.z; l3 += y3 * w.w;
#pragma unroll
    for (int o = 16; o; o >>= 1) {
        l0 += __shfl_xor_sync(0xffffffffu, l0, o);
        l1 += __shfl_xor_sync(0xffffffffu, l1, o);
        l2 += __shfl_xor_sync(0xffffffffu, l2, o);
        l3 += __shfl_xor_sync(0xffffffffu, l3, o);
    }
    __shared__ float lr[8][4];
    if (lane == 0) { lr[warp][0] = l0; lr[warp][1] = l1; lr[warp][2] = l2; lr[warp][3] = l3; }
    __syncthreads();
    if (t == 0) {
        float L[NE];
#pragma unroll
        for (int e = 0; e < NE; e++) {
            float a = gate_b[e];
#pragma unroll
            for (int wg = 0; wg < 8; wg++) a += lr[wg][e];
            L[e] = a;
        }
        float m = L[0];
#pragma unroll
        for (int e = 1; e < NE; e++) m = fmaxf(m, L[e]);
        float sum = 0.f, ew[NE];
#pragma unroll
        for (int e = 0; e < NE; e++) { ew[e] = expf(L[e] - m); sum += ew[e]; }
        const float inv = 1.0f / sum;
#pragma unroll
        for (int e = 0; e < NE; e++) g_gate[row * NE + e] = ew[e] * inv;
#pragma unroll
        for (int c = 0; c < NC; c++) {
            float a = 0.f;
#pragma unroll
            for (int e = 0; e < NE; e++) a += ew[e] * inv * ex_b2[e * NC + c];
            out[row * NC + c] = a;
        }
    }
}

// ===== K1: fold ln gain into w1, transpose to [e*H+h][d] K-major, cast fp16 =====
__global__ __launch_bounds__(256) void fold_w1_kernel(
    const float* __restrict__ w1, const float* __restrict__ lng)
{
    __shared__ float tile[32][33];
    const int tx = threadIdx.x, ty = threadIdx.y;
    const int h0 = blockIdx.x * 32, d0 = blockIdx.y * 32, e = blockIdx.z;
#pragma unroll
    for (int i = 0; i < 4; i++) {
        const int d = d0 + ty + i * 8;
        tile[ty + i * 8][tx] = w1[((size_t)e * DIM + d) * HID + h0 + tx] * lng[e * DIM + d];
    }
    __syncthreads();
#pragma unroll
    for (int i = 0; i < 4; i++) {
        const int h = h0 + ty + i * 8;
        g_w1h[((size_t)e * HID + h) * DIM + d0 + tx] = __float2half_rn(tile[tx][ty + i * 8]);
    }
}

// ===== K2: b1f[e][h] = b1[e][h] + sum_d lnb[e][d] * w1[e][d][h] =====
__global__ __launch_bounds__(256) void fold_b1_kernel(
    const float* __restrict__ w1, const float* __restrict__ lnb,
    const float* __restrict__ b1)
{
    const int e = blockIdx.y;
    const int h = blockIdx.x * 256 + threadIdx.x;
    float acc = b1[e * HID + h];
    const float* wp = w1 + (size_t)e * DIM * HID + h;
    const float* bp = lnb + e * DIM;
#pragma unroll 4
    for (int d = 0; d < DIM; d++) acc += bp[d] * wp[(size_t)d * HID];
    g_b1f[e * HID + h] = acc;
}

// ============== K3: mma.sync fp16 GEMM, 3 CTA/SM (24 warps), fused epilogue ==============
// 128x64 tile, warp layout 4x2 (warp tile 32x32, acc=32 regs). Occupancy is the
// binding resource (R8/R10 evidence), so tile shrinks to fit 3 CTAs in regs+smem.
__global__ __launch_bounds__(256, 3) void gemm_kernel(
    const float* __restrict__ ex_w2, float* __restrict__ out)
{
    extern __shared__ __align__(1024) char smem[];
    float* sred = (float*)(smem + SRED_OFF);
    const uint32_t sb = smem_u32(smem);
    const int t = threadIdx.x;
    const int warp = t >> 5, lane = t & 31;
    const int row0 = blockIdx.x * BM;
    const int n0 = blockIdx.y * BN;
    const int wm = warp >> 1;      // 0..3 -> 32-row band
    const int wn = warp & 1;       // 0..1 -> 32-col band

    float acc[2][4][4];
#pragma unroll
    for (int mi = 0; mi < 2; mi++)
#pragma unroll
        for (int nf = 0; nf < 4; nf++)
#pragma unroll
            for (int q = 0; q < 4; q++) acc[mi][nf][q] = 0.f;

    // ---- loader: A rows lrow+32j (j=0..3), B rows lrow+32j (j=0..1) ----
    const int lrow = t >> 3, lc = t & 7;
    const uint32_t ldst = lrow * 128 + ((lc ^ (lrow & 7)) * 16);   // + j*4096
    const char* gA = (const char*)(g_normed_h + (size_t)(row0 + lrow) * DIM) + lc * 16;
    const char* gB = (const char*)(g_w1h + (size_t)(n0 + lrow) * DIM) + lc * 16;

    // ---- ldmatrix base offsets per ks ----
    uint32_t aoff0[4], boff0[4];
    {
        const int arow = wm * 32 + (lane & 15);
        const int brow = wn * 32 + (lane & 15);
        const int hi = lane >> 4;
#pragma unroll
        for (int ks = 0; ks < 4; ks++) {
            const int c = ks * 2 + hi;
            aoff0[ks] = arow * 128 + ((c ^ (arow & 7)) * 16);
            boff0[ks] = ASTG + brow * 128 + ((c ^ (brow & 7)) * 16);
        }
    }

    // ---- prologue: fill STAGES-1 stages ----
#pragma unroll
    for (int s = 0; s < STAGES - 1; s++) {
        const uint32_t sbase = sb + s * STG;
#pragma unroll
        for (int j = 0; j < 4; j++) cp16(sbase + ldst + j * 4096, gA + j * 65536);
#pragma unroll
        for (int j = 0; j < 2; j++) cp16(sbase + ASTG + ldst + j * 4096, gB + j * 65536);
        gA += 128; gB += 128;
        CP_COMMIT();
    }

    int stage = 0, wstage = STAGES - 1;
    for (int it = 0; it < KITERS; it++) {
        CP_WAIT(STAGES - 2);
        __syncthreads();
        if (it + STAGES - 1 < KITERS) {
            const uint32_t sbase = sb + wstage * STG;
#pragma unroll
            for (int j = 0; j < 4; j++) cp16(sbase + ldst + j * 4096, gA + j * 65536);
#pragma unroll
            for (int j = 0; j < 2; j++) cp16(sbase + ASTG + ldst + j * 4096, gB + j * 65536);
            gA += 128; gB += 128;
        }
        CP_COMMIT();
        wstage = (wstage + 1 == STAGES) ? 0 : wstage + 1;

        const uint32_t sS = sb + stage * STG;
        stage = (stage + 1 == STAGES) ? 0 : stage + 1;
#pragma unroll
        for (int ks = 0; ks < 4; ks++) {
            uint32_t a[2][4], bf[4][2];
            const uint32_t ab = sS + aoff0[ks];
            const uint32_t bb = sS + boff0[ks];
            LDSM4(a[0], ab);
            LDSM4(a[1], ab + 2048);
#pragma unroll
            for (int g = 0; g < 2; g++) {
                uint32_t r[4];
                LDSM4(r, bb + g * 2048);
                bf[2 * g][0] = r[0];     bf[2 * g][1] = r[2];
                bf[2 * g + 1][0] = r[1]; bf[2 * g + 1][1] = r[3];
            }
#pragma unroll
            for (int mi = 0; mi < 2; mi++)
#pragma unroll
                for (int nf = 0; nf < 4; nf++)
                    MMA16816(acc[mi][nf], a[mi], bf[nf]);
        }
    }
    CP_WAIT(0);

    // ---- epilogue: +b1f, exact GELU, x w2 (H->3), smem row-reduce, gated atomics ----
    const int e = blockIdx.y >> 5;   // expert = n0 / HID  (HID/BN = 32 tiles/expert)
    for (int i = t; i < BM * NC; i += 256) sred[i] = 0.f;
    __syncthreads();

#pragma unroll
    for (int mi = 0; mi < 2; mi++) {
        float s00 = 0.f, s01 = 0.f, s02 = 0.f;
        float s10 = 0.f, s11 = 0.f, s12 = 0.f;
#pragma unroll
        for (int nf = 0; nf < 4; nf++) {
            const int n = n0 + wn * 32 + nf * 8 + (lane & 3) * 2;
            const float b1a = __ldg(&g_b1f[n]), b1b = __ldg(&g_b1f[n + 1]);
            const float wa0 = __ldg(&ex_w2[n * 3 + 0]);
            const float wa1 = __ldg(&ex_w2[n * 3 + 1]);
            const float wa2 = __ldg(&ex_w2[n * 3 + 2]);
            const float wb0 = __ldg(&ex_w2[n * 3 + 3]);
            const float wb1 = __ldg(&ex_w2[n * 3 + 4]);
            const float wb2 = __ldg(&ex_w2[n * 3 + 5]);
            const float v00 = gelu_exact(acc[mi][nf][0] + b1a);
            const float v01 = gelu_exact(acc[mi][nf][1] + b1b);
            const float v10 = gelu_exact(acc[mi][nf][2] + b1a);
            const float v11 = gelu_exact(acc[mi][nf][3] + b1b);
            s00 += v00 * wa0 + v01 * wb0;
            s01 += v00 * wa1 + v01 * wb1;
            s02 += v00 * wa2 + v01 * wb2;
            s10 += v10 * wa0 + v11 * wb0;
            s11 += v10 * wa1 + v11 * wb1;
            s12 += v10 * wa2 + v11 * wb2;
        }
#pragma unroll
        for (int o = 2; o; o >>= 1) {
            s00 += __shfl_xor_sync(0xffffffffu, s00, o);
            s01 += __shfl_xor_sync(0xffffffffu, s01, o);
            s02 += __shfl_xor_sync(0xffffffffu, s02, o);
            s10 += __shfl_xor_sync(0xffffffffu, s10, o);
            s11 += __shfl_xor_sync(0xffffffffu, s11, o);
            s12 += __shfl_xor_sync(0xffffffffu, s12, o);
        }
        if ((lane & 3) == 0) {
            const int rl = wm * 32 + mi * 16 + (lane >> 2);
            atomicAdd(&sred[rl * NC + 0], s00);
            atomicAdd(&sred[rl * NC + 1], s01);
            atomicAdd(&sred[rl * NC + 2], s02);
            atomicAdd(&sred[(rl + 8) * NC + 0], s10);
            atomicAdd(&sred[(rl + 8) * NC + 1], s11);
            atomicAdd(&sred[(rl + 8) * NC + 2], s12);
        }
    }
    __syncthreads();

    if (t < BM) {
        const int row = row0 + t;
        const float gw = g_gate[row * NE + e];
        atomicAdd(&out[row * NC + 0], gw * sred[t * NC + 0]);
        atomicAdd(&out[row * NC + 1], gw * sred[t * NC + 1]);
        atomicAdd(&out[row * NC + 2], gw * sred[t * NC + 2]);
    }
}

// ==================================================================================
extern "C" void kernel_launch(void* const* d_in, const int* in_sizes, int n_in,
                              void* d_out, int out_size)
{
    const float* x       = (const float*)d_in[0];
    const float* gln_g   = (const float*)d_in[1];
    const float* gln_b   = (const float*)d_in[2];
    const float* gate_w  = (const float*)d_in[3];
    const float* gate_b  = (const float*)d_in[4];
    const float* ex_ln_g = (const float*)d_in[5];
    const float* ex_ln_b = (const float*)d_in[6];
    const float* ex_w1   = (const float*)d_in[7];
    const float* ex_b1   = (const float*)d_in[8];
    const float* ex_w2   = (const float*)d_in[9];
    const float* ex_b2   = (const float*)d_in[10];
    float* out = (float*)d_out;

    cudaFuncSetAttribute(gemm_kernel, cudaFuncAttributeMaxDynamicSharedMemorySize, DYN_SMEM);

    ln_gate_kernel<<<B_TOK, 256>>>(x, gln_g, gln_b, gate_w, gate_b, ex_b2, out);
    fold_w1_kernel<<<dim3(HID / 32, DIM / 32, NE), dim3(32, 8)>>>(ex_w1, ex_ln_g);
    fold_b1_kernel<<<dim3(HID / 256, NE), 256>>>(ex_w1, ex_ln_b, ex_b1);
    gemm_kernel<<<dim3(B_TOK / BM, NTOT / BN), 256, DYN_SMEM>>>(ex_w2, out);
}

// round 14
// speedup vs baseline: 1.2008x; 1.0932x over previous
#include <cuda_runtime.h>
#include <cuda_fp16.h>
#include <math.h>
#include <stdint.h>

#define B_TOK 16384
#define DIM   1024          // K
#define HID   2048
#define NE    4
#define NC    3
#define NTOT  (NE * HID)    // 8192 rows of folded W1 (N dimension)

#define BM 128
#define BN 64
#define BK 64               // 64 halfs = 128B per row
#define KITERS (DIM / BK)   // 16
#define STAGES 3
#define ASTG 16384          // A stage: 128*64*2
#define BSTG 8192           // B stage: 64*64*2
#define STG  (ASTG + BSTG)  // 24 KB / stage
#define SRED_OFF (STAGES * STG)              // 73728
#define DYN_SMEM (SRED_OFF + BM * NC * 4)    // 75264 (~73.5 KB) -> 3 CTA/SM

// ---- device scratch (allocation-free) ----
__device__ __align__(1024) __half g_normed_h[(size_t)B_TOK * DIM];  // 32 MB
__device__ __align__(1024) __half g_w1h[(size_t)NTOT * DIM];        // 16 MB (K-major, g-folded)
__device__ __align__(1024) float  g_b1f[NTOT];                      // b1 + lnb@w1
__device__ __align__(1024) float  g_gate[B_TOK * NE];

// ============================ PTX helpers (sm_80-safe only) ============================
__device__ __forceinline__ uint32_t smem_u32(const void* p) {
    uint32_t a;
    asm("{ .reg .u64 t; cvta.to.shared.u64 t, %1; cvt.u32.u64 %0, t; }" : "=r"(a) : "l"(p));
    return a;
}
__device__ __forceinline__ void cp16(uint32_t sa, const void* g) {
    asm volatile("cp.async.cg.shared.global [%0], [%1], 16;" :: "r"(sa), "l"(g) : "memory");
}
#define CP_COMMIT() asm volatile("cp.async.commit_group;" ::: "memory")
#define CP_WAIT(n)  asm volatile("cp.async.wait_group %0;" :: "n"(n) : "memory")

#define LDSM4(r, a) \
    asm volatile("ldmatrix.sync.aligned.m8n8.x4.shared.b16 {%0,%1,%2,%3}, [%4];" \
        : "=r"((r)[0]), "=r"((r)[1]), "=r"((r)[2]), "=r"((r)[3]) : "r"(a))

#define MMA16816(d, a, b) \
    asm volatile("mma.sync.aligned.m16n8k16.row.col.f32.f16.f16.f32 " \
        "{%0,%1,%2,%3}, {%4,%5,%6,%7}, {%8,%9}, {%0,%1,%2,%3};" \
        : "+f"((d)[0]), "+f"((d)[1]), "+f"((d)[2]), "+f"((d)[3]) \
        : "r"((a)[0]), "r"((a)[1]), "r"((a)[2]), "r"((a)[3]), "r"((b)[0]), "r"((b)[1]))

__device__ __forceinline__ float gelu_exact(float v) {
    return 0.5f * v * (1.0f + erff(v * 0.70710678118654752f));
}

// ============== K0: LayerNorm + gate softmax + out bias init ==============
__global__ __launch_bounds__(256) void ln_gate_kernel(
    const float* __restrict__ x,
    const float* __restrict__ gln_g, const float* __restrict__ gln_b,
    const float* __restrict__ gate_w, const float* __restrict__ gate_b,
    const float* __restrict__ ex_b2, float* __restrict__ out)
{
    const int row = blockIdx.x, t = threadIdx.x;
    const int lane = t & 31, warp = t >> 5;

    const float4 xv = *(const float4*)(x + (size_t)row * DIM + t * 4);
    float s  = xv.x + xv.y + xv.z + xv.w;
    float ss = xv.x * xv.x + xv.y * xv.y + xv.z * xv.z + xv.w * xv.w;
#pragma unroll
    for (int o = 16; o; o >>= 1) {
        s  += __shfl_xor_sync(0xffffffffu, s, o);
        ss += __shfl_xor_sync(0xffffffffu, ss, o);
    }
    __shared__ float rs[8], rss[8];
    if (lane == 0) { rs[warp] = s; rss[warp] = ss; }
    __syncthreads();
    s = 0.f; ss = 0.f;
#pragma unroll
    for (int w = 0; w < 8; w++) { s += rs[w]; ss += rss[w]; }
    const float mu = s * (1.0f / DIM);
    const float var = ss * (1.0f / DIM) - mu * mu;
    const float rstd = rsqrtf(var + 1e-5f);

    float4 nv;
    nv.x = (xv.x - mu) * rstd; nv.y = (xv.y - mu) * rstd;
    nv.z = (xv.z - mu) * rstd; nv.w = (xv.w - mu) * rstd;
    __half2* np = (__half2*)(g_normed_h + (size_t)row * DIM + t * 4);
    np[0] = __floats2half2_rn(nv.x, nv.y);
    np[1] = __floats2half2_rn(nv.z, nv.w);

    const int d0 = t * 4;
    const float4 gg = *(const float4*)(gln_g + d0);
    const float4 gb = *(const float4*)(gln_b + d0);
    float y0 = fmaf(nv.x, gg.x, gb.x), y1 = fmaf(nv.y, gg.y, gb.y);
    float y2 = fmaf(nv.z, gg.z, gb.z), y3 = fmaf(nv.w, gg.w, gb.w);
    float l0 = 0.f, l1 = 0.f, l2 = 0.f, l3 = 0.f;
    float4 w;
    w = *(const float4*)(gate_w + (size_t)(d0 + 0) * NE);
    l0 += y0 * w.x; l1 += y0 * w.y; l2 += y0 * w.z; l3 += y0 * w.w;
    w = *(const float4*)(gate_w + (size_t)(d0 + 1) * NE);
    l0 += y1 * w.x; l1 += y1 * w.y; l2 += y1 * w.z; l3 += y1 * w.w;
    w = *(const float4*)(gate_w + (size_t)(d0 + 2) * NE);
    l0 += y2 * w.x; l1 += y2 * w.y; l2 += y2 * w.z; l3 += y2 * w.w;
    w = *(const float4*)(gate_w + (size_t)(d0 + 3) * NE);
    l0 += y3 * w.x; l1 += y3 * w.y; l2 += y3 * w.z; l3 += y3 * w.w;
#pragma unroll
    for (int o = 16; o; o >>= 1) {
        l0 += __shfl_xor_sync(0xffffffffu, l0, o);
        l1 += __shfl_xor_sync(0xffffffffu, l1, o);
        l2 += __shfl_xor_sync(0xffffffffu, l2, o);
        l3 += __shfl_xor_sync(0xffffffffu, l3, o);
    }
    __shared__ float lr[8][4];
    if (lane == 0) { lr[warp][0] = l0; lr[warp][1] = l1; lr[warp][2] = l2; lr[warp][3] = l3; }
    __syncthreads();
    if (t == 0) {
        float L[NE];
#pragma unroll
        for (int e = 0; e < NE; e++) {
            float a = gate_b[e];
#pragma unroll
            for (int wg = 0; wg < 8; wg++) a += lr[wg][e];
            L[e] = a;
        }
        float m = L[0];
#pragma unroll
        for (int e = 1; e < NE; e++) m = fmaxf(m, L[e]);
        float sum = 0.f, ew[NE];
#pragma unroll
        for (int e = 0; e < NE; e++) { ew[e] = expf(L[e] - m); sum += ew[e]; }
        const float inv = 1.0f / sum;
#pragma unroll
        for (int e = 0; e < NE; e++) g_gate[row * NE + e] = ew[e] * inv;
#pragma unroll
        for (int c = 0; c < NC; c++) {
            float a = 0.f;
#pragma unroll
            for (int e = 0; e < NE; e++) a += ew[e] * inv * ex_b2[e * NC + c];
            out[row * NC + c] = a;
        }
    }
}

// ===== K1a: seed b1f = b1 (re-done every replay for determinism) =====
__global__ __launch_bounds__(256) void b1_init_kernel(const float* __restrict__ b1)
{
    const int i = blockIdx.x * 256 + threadIdx.x;
    g_b1f[i] = b1[i];
}

// ===== K1b: fold ln gain into w1 (K-major fp16) AND accumulate lnb@w1 into b1f =====
// Single pass over w1: tile holds raw*lng for the transpose; the raw value also
// feeds the b1 partial (raw*lnb), reduced per column in smem, one REDG per (h, d-block).
__global__ __launch_bounds__(256) void fold_w1_kernel(
    const float* __restrict__ w1, const float* __restrict__ lng,
    const float* __restrict__ lnb)
{
    __shared__ float tile[32][33];
    __shared__ float bpart[32];
    const int tx = threadIdx.x, ty = threadIdx.y;
    const int h0 = blockIdx.x * 32, d0 = blockIdx.y * 32, e = blockIdx.z;

    float bsum = 0.f;
#pragma unroll
    for (int i = 0; i < 4; i++) {
        const int d = d0 + ty + i * 8;
        const float raw = w1[((size_t)e * DIM + d) * HID + h0 + tx];
        tile[ty + i * 8][tx] = raw * __ldg(&lng[e * DIM + d]);
        bsum += raw * __ldg(&lnb[e * DIM + d]);
    }
    if (ty == 0) bpart[tx] = 0.f;
    __syncthreads();
    atomicAdd(&bpart[tx], bsum);
#pragma unroll
    for (int i = 0; i < 4; i++) {
        const int h = h0 + ty + i * 8;
        g_w1h[((size_t)e * HID + h) * DIM + d0 + tx] = __float2half_rn(tile[tx][ty + i * 8]);
    }
    __syncthreads();
    if (ty == 0) atomicAdd(&g_b1f[e * HID + h0 + tx], bpart[tx]);
}

// ============== K3: mma.sync fp16 GEMM, 3 CTA/SM, warp-staggered k-steps ==============
// Identical to R11 except each warp's k-step order is rotated by (warp&3) — baked
// into the offset tables so indexing stays static. Breaks the barrier-phase-locked
// LDSM/MMA convoys: warps in one SMSP alternate smem-phase vs tensor-phase.
__global__ __launch_bounds__(256, 3) void gemm_kernel(
    const float* __restrict__ ex_w2, float* __restrict__ out)
{
    extern __shared__ __align__(1024) char smem[];
    float* sred = (float*)(smem + SRED_OFF);
    const uint32_t sb = smem_u32(smem);
    const int t = threadIdx.x;
    const int warp = t >> 5, lane = t & 31;
    const int row0 = blockIdx.x * BM;
    const int n0 = blockIdx.y * BN;
    const int wm = warp >> 1;      // 0..3 -> 32-row band
    const int wn = warp & 1;       // 0..1 -> 32-col band

    float acc[2][4][4];
#pragma unroll
    for (int mi = 0; mi < 2; mi++)
#pragma unroll
        for (int nf = 0; nf < 4; nf++)
#pragma unroll
            for (int q = 0; q < 4; q++) acc[mi][nf][q] = 0.f;

    // ---- loader: A rows lrow+32j (j=0..3), B rows lrow+32j (j=0..1) ----
    const int lrow = t >> 3, lc = t & 7;
    const uint32_t ldst = lrow * 128 + ((lc ^ (lrow & 7)) * 16);   // + j*4096
    const char* gA = (const char*)(g_normed_h + (size_t)(row0 + lrow) * DIM) + lc * 16;
    const char* gB = (const char*)(g_w1h + (size_t)(n0 + lrow) * DIM) + lc * 16;

    // ---- ldmatrix offsets: entry j corresponds to k-step (j + warp) & 3 ----
    uint32_t aoff0[4], boff0[4];
    {
        const int arow = wm * 32 + (lane & 15);
        const int brow = wn * 32 + (lane & 15);
        const int hi = lane >> 4;
#pragma unroll
        for (int j = 0; j < 4; j++) {
            const int ks = (j + warp) & 3;
            const int c = ks * 2 + hi;
            aoff0[j] = arow * 128 + ((c ^ (arow & 7)) * 16);
            boff0[j] = ASTG + brow * 128 + ((c ^ (brow & 7)) * 16);
        }
    }

    // ---- prologue: fill STAGES-1 stages ----
#pragma unroll
    for (int s = 0; s < STAGES - 1; s++) {
        const uint32_t sbase = sb + s * STG;
#pragma unroll
        for (int j = 0; j < 4; j++) cp16(sbase + ldst + j * 4096, gA + j * 65536);
#pragma unroll
        for (int j = 0; j < 2; j++) cp16(sbase + ASTG + ldst + j * 4096, gB + j * 65536);
        gA += 128; gB += 128;
        CP_COMMIT();
    }

    int stage = 0, wstage = STAGES - 1;
    for (int it = 0; it < KITERS; it++) {
        CP_WAIT(STAGES - 2);
        __syncthreads();
        if (it + STAGES - 1 < KITERS) {
            const uint32_t sbase = sb + wstage * STG;
#pragma unroll
            for (int j = 0; j < 4; j++) cp16(sbase + ldst + j * 4096, gA + j * 65536);
#pragma unroll
            for (int j = 0; j < 2; j++) cp16(sbase + ASTG + ldst + j * 4096, gB + j * 65536);
            gA += 128; gB += 128;
        }
        CP_COMMIT();
        wstage = (wstage + 1 == STAGES) ? 0 : wstage + 1;

        const uint32_t sS = sb + stage * STG;
        stage = (stage + 1 == STAGES) ? 0 : stage + 1;
#pragma unroll
        for (int ks = 0; ks < 4; ks++) {
            uint32_t a[2][4], bf[4][2];
            const uint32_t ab = sS + aoff0[ks];
            const uint32_t bb = sS + boff0[ks];
            LDSM4(a[0], ab);
            LDSM4(a[1], ab + 2048);
#pragma unroll
            for (int g = 0; g < 2; g++) {
                uint32_t r[4];
                LDSM4(r, bb + g * 2048);
                bf[2 * g][0] = r[0];     bf[2 * g][1] = r[2];
                bf[2 * g + 1][0] = r[1]; bf[2 * g + 1][1] = r[3];
            }
#pragma unroll
            for (int mi = 0; mi < 2; mi++)
#pragma unroll
                for (int nf = 0; nf < 4; nf++)
                    MMA16816(acc[mi][nf], a[mi], bf[nf]);
        }
    }
    CP_WAIT(0);

    // ---- epilogue: +b1f, exact GELU, x w2 (H->3), smem row-reduce, gated atomics ----
    const int e = blockIdx.y >> 5;   // expert = n0 / HID  (HID/BN = 32 tiles/expert)
    for (int i = t; i < BM * NC; i += 256) sred[i] = 0.f;
    __syncthreads();

#pragma unroll
    for (int mi = 0; mi < 2; mi++) {
        float s00 = 0.f, s01 = 0.f, s02 = 0.f;
        float s10 = 0.f, s11 = 0.f, s12 = 0.f;
#pragma unroll
        for (int nf = 0; nf < 4; nf++) {
            const int n = n0 + wn * 32 + nf * 8 + (lane & 3) * 2;
            const float b1a = __ldg(&g_b1f[n]), b1b = __ldg(&g_b1f[n + 1]);
            const float wa0 = __ldg(&ex_w2[n * 3 + 0]);
            const float wa1 = __ldg(&ex_w2[n * 3 + 1]);
            const float wa2 = __ldg(&ex_w2[n * 3 + 2]);
            const float wb0 = __ldg(&ex_w2[n * 3 + 3]);
            const float wb1 = __ldg(&ex_w2[n * 3 + 4]);
            const float wb2 = __ldg(&ex_w2[n * 3 + 5]);
            const float v00 = gelu_exact(acc[mi][nf][0] + b1a);
            const float v01 = gelu_exact(acc[mi][nf][1] + b1b);
            const float v10 = gelu_exact(acc[mi][nf][2] + b1a);
            const float v11 = gelu_exact(acc[mi][nf][3] + b1b);
            s00 += v00 * wa0 + v01 * wb0;
            s01 += v00 * wa1 + v01 * wb1;
            s02 += v00 * wa2 + v01 * wb2;
            s10 += v10 * wa0 + v11 * wb0;
            s11 += v10 * wa1 + v11 * wb1;
            s12 += v10 * wa2 + v11 * wb2;
        }
#pragma unroll
        for (int o = 2; o; o >>= 1) {
            s00 += __shfl_xor_sync(0xffffffffu, s00, o);
            s01 += __shfl_xor_sync(0xffffffffu, s01, o);
            s02 += __shfl_xor_sync(0xffffffffu, s02, o);
            s10 += __shfl_xor_sync(0xffffffffu, s10, o);
            s11 += __shfl_xor_sync(0xffffffffu, s11, o);
            s12 += __shfl_xor_sync(0xffffffffu, s12, o);
        }
        if ((lane & 3) == 0) {
            const int rl = wm * 32 + mi * 16 + (lane >> 2);
            atomicAdd(&sred[rl * NC + 0], s00);
            atomicAdd(&sred[rl * NC + 1], s01);
            atomicAdd(&sred[rl * NC + 2], s02);
            atomicAdd(&sred[(rl + 8) * NC + 0], s10);
            atomicAdd(&sred[(rl + 8) * NC + 1], s11);
            atomicAdd(&sred[(rl + 8) * NC + 2], s12);
        }
    }
    __syncthreads();

    if (t < BM) {
        const int row = row0 + t;
        const float gw = g_gate[row * NE + e];
        atomicAdd(&out[row * NC + 0], gw * sred[t * NC + 0]);
        atomicAdd(&out[row * NC + 1], gw * sred[t * NC + 1]);
        atomicAdd(&out[row * NC + 2], gw * sred[t * NC + 2]);
    }
}

// ==================================================================================
extern "C" void kernel_launch(void* const* d_in, const int* in_sizes, int n_in,
                              void* d_out, int out_size)
{
    const float* x       = (const float*)d_in[0];
    const float* gln_g   = (const float*)d_in[1];
    const float* gln_b   = (const float*)d_in[2];
    const float* gate_w  = (const float*)d_in[3];
    const float* gate_b  = (const float*)d_in[4];
    const float* ex_ln_g = (const float*)d_in[5];
    const float* ex_ln_b = (const float*)d_in[6];
    const float* ex_w1   = (const float*)d_in[7];
    const float* ex_b1   = (const float*)d_in[8];
    const float* ex_w2   = (const float*)d_in[9];
    const float* ex_b2   = (const float*)d_in[10];
    float* out = (float*)d_out;

    cudaFuncSetAttribute(gemm_kernel, cudaFuncAttributeMaxDynamicSharedMemorySize, DYN_SMEM);

    ln_gate_kernel<<<B_TOK, 256>>>(x, gln_g, gln_b, gate_w, gate_b, ex_b2, out);
    b1_init_kernel<<<NTOT / 256, 256>>>(ex_b1);
    fold_w1_kernel<<<dim3(HID / 32, DIM / 32, NE), dim3(32, 8)>>>(ex_w1, ex_ln_g, ex_ln_b);
    gemm_kernel<<<dim3(B_TOK / BM, NTOT / BN), 256, DYN_SMEM>>>(ex_w2, out);
}

// round 16
// speedup vs baseline: 1.2169x; 1.0133x over previous
#include <cuda_runtime.h>
#include <cuda_fp16.h>
#include <math.h>
#include <stdint.h>

#define B_TOK 16384
#define DIM   1024          // K
#define HID   2048
#define NE    4
#define NC    3
#define NTOT  (NE * HID)    // 8192 rows of folded W1 (N dimension)

#define BM 128
#define BN 64
#define BK 64               // 64 halfs = 128B per row
#define KITERS (DIM / BK)   // 16
#define STAGES 3
#define ASTG 16384          // A stage: 128*64*2
#define BSTG 8192           // B stage: 64*64*2
#define STG  (ASTG + BSTG)  // 24 KB / stage
#define SRED_OFF (STAGES * STG)              // 73728
#define DYN_SMEM (SRED_OFF + BM * NC * 4)    // 75264 (~73.5 KB) -> 3 CTA/SM

// ---- device scratch (allocation-free) ----
__device__ __align__(1024) __half g_normed_h[(size_t)B_TOK * DIM];  // 32 MB
__device__ __align__(1024) __half g_w1h[(size_t)NTOT * DIM];        // 16 MB (K-major, g-folded)
__device__ __align__(1024) float  g_b1f[NTOT];                      // b1 + lnb@w1
__device__ __align__(1024) float  g_gate[B_TOK * NE];

// ============================ PTX helpers (sm_80-safe only) ============================
__device__ __forceinline__ uint32_t smem_u32(const void* p) {
    uint32_t a;
    asm("{ .reg .u64 t; cvta.to.shared.u64 t, %1; cvt.u32.u64 %0, t; }" : "=r"(a) : "l"(p));
    return a;
}
__device__ __forceinline__ void cp16(uint32_t sa, const void* g) {
    asm volatile("cp.async.cg.shared.global [%0], [%1], 16;" :: "r"(sa), "l"(g) : "memory");
}
#define CP_COMMIT() asm volatile("cp.async.commit_group;" ::: "memory")
#define CP_WAIT(n)  asm volatile("cp.async.wait_group %0;" :: "n"(n) : "memory")

#define LDSM4(r, a) \
    asm volatile("ldmatrix.sync.aligned.m8n8.x4.shared.b16 {%0,%1,%2,%3}, [%4];" \
        : "=r"((r)[0]), "=r"((r)[1]), "=r"((r)[2]), "=r"((r)[3]) : "r"(a))

#define MMA16816(d, a, b) \
    asm volatile("mma.sync.aligned.m16n8k16.row.col.f32.f16.f16.f32 " \
        "{%0,%1,%2,%3}, {%4,%5,%6,%7}, {%8,%9}, {%0,%1,%2,%3};" \
        : "+f"((d)[0]), "+f"((d)[1]), "+f"((d)[2]), "+f"((d)[3]) \
        : "r"((a)[0]), "r"((a)[1]), "r"((a)[2]), "r"((a)[3]), "r"((b)[0]), "r"((b)[1]))

__device__ __forceinline__ float gelu_exact(float v) {
    return 0.5f * v * (1.0f + erff(v * 0.70710678118654752f));
}

// ============== K0: LayerNorm + gate softmax + out bias init ==============
// Warp-per-row: 8 rows per 256-thread block, shfl-only reductions, no barriers,
// no smem. Each lane keeps its 32 row elements in registers across both passes.
__global__ __launch_bounds__(256) void ln_gate_kernel(
    const float* __restrict__ x,
    const float* __restrict__ gln_g, const float* __restrict__ gln_b,
    const float* __restrict__ gate_w, const float* __restrict__ gate_b,
    const float* __restrict__ ex_b2, float* __restrict__ out)
{
    const int warp = threadIdx.x >> 5, lane = threadIdx.x & 31;
    const int row = blockIdx.x * 8 + warp;

    const float4* xp = (const float4*)(x + (size_t)row * DIM);
    float4 xv[8];
#pragma unroll
    for (int j = 0; j < 8; j++) xv[j] = xp[lane + j * 32];

    float s = 0.f, ss = 0.f;
#pragma unroll
    for (int j = 0; j < 8; j++) {
        s  += xv[j].x + xv[j].y + xv[j].z + xv[j].w;
        ss += xv[j].x * xv[j].x + xv[j].y * xv[j].y
            + xv[j].z * xv[j].z + xv[j].w * xv[j].w;
    }
#pragma unroll
    for (int o = 16; o; o >>= 1) {
        s  += __shfl_xor_sync(0xffffffffu, s, o);
        ss += __shfl_xor_sync(0xffffffffu, ss, o);
    }
    const float mu = s * (1.0f / DIM);
    const float var = ss * (1.0f / DIM) - mu * mu;
    const float rstd = rsqrtf(var + 1e-5f);

    const float4* ggp = (const float4*)gln_g;
    const float4* gbp = (const float4*)gln_b;
    const float4* gwp = (const float4*)gate_w;   // row d of gate_w = float4
    __half2* np = (__half2*)(g_normed_h + (size_t)row * DIM);

    float l0 = 0.f, l1 = 0.f, l2 = 0.f, l3 = 0.f;
#pragma unroll
    for (int j = 0; j < 8; j++) {
        const int f = lane + j * 32;       // float4 index within row
        float4 nv;
        nv.x = (xv[j].x - mu) * rstd; nv.y = (xv[j].y - mu) * rstd;
        nv.z = (xv[j].z - mu) * rstd; nv.w = (xv[j].w - mu) * rstd;
        np[2 * f]     = __floats2half2_rn(nv.x, nv.y);
        np[2 * f + 1] = __floats2half2_rn(nv.z, nv.w);

        const float4 gg = ggp[f], gb = gbp[f];
        const float y0 = fmaf(nv.x, gg.x, gb.x);
        const float y1 = fmaf(nv.y, gg.y, gb.y);
        const float y2 = fmaf(nv.z, gg.z, gb.z);
        const float y3 = fmaf(nv.w, gg.w, gb.w);
        const int d0 = f * 4;
        float4 w;
        w = gwp[d0 + 0]; l0 += y0 * w.x; l1 += y0 * w.y; l2 += y0 * w.z; l3 += y0 * w.w;
        w = gwp[d0 + 1]; l0 += y1 * w.x; l1 += y1 * w.y; l2 += y1 * w.z; l3 += y1 * w.w;
        w = gwp[d0 + 2]; l0 += y2 * w.x; l1 += y2 * w.y; l2 += y2 * w.z; l3 += y2 * w.w;
        w = gwp[d0 + 3]; l0 += y3 * w.x; l1 += y3 * w.y; l2 += y3 * w.z; l3 += y3 * w.w;
    }
#pragma unroll
    for (int o = 16; o; o >>= 1) {
        l0 += __shfl_xor_sync(0xffffffffu, l0, o);
        l1 += __shfl_xor_sync(0xffffffffu, l1, o);
        l2 += __shfl_xor_sync(0xffffffffu, l2, o);
        l3 += __shfl_xor_sync(0xffffffffu, l3, o);
    }

    if (lane == 0) {
        float L[NE] = { l0 + gate_b[0], l1 + gate_b[1], l2 + gate_b[2], l3 + gate_b[3] };
        float m = L[0];
#pragma unroll
        for (int e = 1; e < NE; e++) m = fmaxf(m, L[e]);
        float sum = 0.f, ew[NE];
#pragma unroll
        for (int e = 0; e < NE; e++) { ew[e] = expf(L[e] - m); sum += ew[e]; }
        const float inv = 1.0f / sum;
#pragma unroll
        for (int e = 0; e < NE; e++) g_gate[row * NE + e] = ew[e] * inv;
#pragma unroll
        for (int c = 0; c < NC; c++) {
            float a = 0.f;
#pragma unroll
            for (int e = 0; e < NE; e++) a += ew[e] * inv * ex_b2[e * NC + c];
            out[row * NC + c] = a;
        }
    }
}

// ===== K1a: seed b1f = b1 (re-done every replay for determinism) =====
__global__ __launch_bounds__(256) void b1_init_kernel(const float* __restrict__ b1)
{
    const int i = blockIdx.x * 256 + threadIdx.x;
    g_b1f[i] = b1[i];
}

// ===== K1b: fold ln gain into w1 (K-major fp16) AND accumulate lnb@w1 into b1f =====
__global__ __launch_bounds__(256) void fold_w1_kernel(
    const float* __restrict__ w1, const float* __restrict__ lng,
    const float* __restrict__ lnb)
{
    __shared__ float tile[32][33];
    __shared__ float bpart[32];
    const int tx = threadIdx.x, ty = threadIdx.y;
    const int h0 = blockIdx.x * 32, d0 = blockIdx.y * 32, e = blockIdx.z;

    float bsum = 0.f;
#pragma unroll
    for (int i = 0; i < 4; i++) {
        const int d = d0 + ty + i * 8;
        const float raw = w1[((size_t)e * DIM + d) * HID + h0 + tx];
        tile[ty + i * 8][tx] = raw * __ldg(&lng[e * DIM + d]);
        bsum += raw * __ldg(&lnb[e * DIM + d]);
    }
    if (ty == 0) bpart[tx] = 0.f;
    __syncthreads();
    atomicAdd(&bpart[tx], bsum);
#pragma unroll
    for (int i = 0; i < 4; i++) {
        const int h = h0 + ty + i * 8;
        g_w1h[((size_t)e * HID + h) * DIM + d0 + tx] = __float2half_rn(tile[tx][ty + i * 8]);
    }
    __syncthreads();
    if (ty == 0) atomicAdd(&g_b1f[e * HID + h0 + tx], bpart[tx]);
}

// ============== K3: mma.sync fp16 GEMM (UNCHANGED from R14 — at the HMMA floor) ==============
__global__ __launch_bounds__(256, 3) void gemm_kernel(
    const float* __restrict__ ex_w2, float* __restrict__ out)
{
    extern __shared__ __align__(1024) char smem[];
    float* sred = (float*)(smem + SRED_OFF);
    const uint32_t sb = smem_u32(smem);
    const int t = threadIdx.x;
    const int warp = t >> 5, lane = t & 31;
    const int row0 = blockIdx.x * BM;
    const int n0 = blockIdx.y * BN;
    const int wm = warp >> 1;
    const int wn = warp & 1;

    float acc[2][4][4];
#pragma unroll
    for (int mi = 0; mi < 2; mi++)
#pragma unroll
        for (int nf = 0; nf < 4; nf++)
#pragma unroll
            for (int q = 0; q < 4; q++) acc[mi][nf][q] = 0.f;

    const int lrow = t >> 3, lc = t & 7;
    const uint32_t ldst = lrow * 128 + ((lc ^ (lrow & 7)) * 16);
    const char* gA = (const char*)(g_normed_h + (size_t)(row0 + lrow) * DIM) + lc * 16;
    const char* gB = (const char*)(g_w1h + (size_t)(n0 + lrow) * DIM) + lc * 16;

    uint32_t aoff0[4], boff0[4];
    {
        const int arow = wm * 32 + (lane & 15);
        const int brow = wn * 32 + (lane & 15);
        const int hi = lane >> 4;
#pragma unroll
        for (int j = 0; j < 4; j++) {
            const int ks = (j + warp) & 3;
            const int c = ks * 2 + hi;
            aoff0[j] = arow * 128 + ((c ^ (arow & 7)) * 16);
            boff0[j] = ASTG + brow * 128 + ((c ^ (brow & 7)) * 16);
        }
    }

#pragma unroll
    for (int s = 0; s < STAGES - 1; s++) {
        const uint32_t sbase = sb + s * STG;
#pragma unroll
        for (int j = 0; j < 4; j++) cp16(sbase + ldst + j * 4096, gA + j * 65536);
#pragma unroll
        for (int j = 0; j < 2; j++) cp16(sbase + ASTG + ldst + j * 4096, gB + j * 65536);
        gA += 128; gB += 128;
        CP_COMMIT();
    }

    int stage = 0, wstage = STAGES - 1;
    for (int it = 0; it < KITERS; it++) {
        CP_WAIT(STAGES - 2);
        __syncthreads();
        if (it + STAGES - 1 < KITERS) {
            const uint32_t sbase = sb + wstage * STG;
#pragma unroll
            for (int j = 0; j < 4; j++) cp16(sbase + ldst + j * 4096, gA + j * 65536);
#pragma unroll
            for (int j = 0; j < 2; j++) cp16(sbase + ASTG + ldst + j * 4096, gB + j * 65536);
            gA += 128; gB += 128;
        }
        CP_COMMIT();
        wstage = (wstage + 1 == STAGES) ? 0 : wstage + 1;

        const uint32_t sS = sb + stage * STG;
        stage = (stage + 1 == STAGES) ? 0 : stage + 1;
#pragma unroll
        for (int ks = 0; ks < 4; ks++) {
            uint32_t a[2][4], bf[4][2];
            const uint32_t ab = sS + aoff0[ks];
            const uint32_t bb = sS + boff0[ks];
            LDSM4(a[0], ab);
            LDSM4(a[1], ab + 2048);
#pragma unroll
            for (int g = 0; g < 2; g++) {
                uint32_t r[4];
                LDSM4(r, bb + g * 2048);
                bf[2 * g][0] = r[0];     bf[2 * g][1] = r[2];
                bf[2 * g + 1][0] = r[1]; bf[2 * g + 1][1] = r[3];
            }
#pragma unroll
            for (int mi = 0; mi < 2; mi++)
#pragma unroll
                for (int nf = 0; nf < 4; nf++)
                    MMA16816(acc[mi][nf], a[mi], bf[nf]);
        }
    }
    CP_WAIT(0);

    const int e = blockIdx.y >> 5;
    for (int i = t; i < BM * NC; i += 256) sred[i] = 0.f;
    __syncthreads();

#pragma unroll
    for (int mi = 0; mi < 2; mi++) {
        float s00 = 0.f, s01 = 0.f, s02 = 0.f;
        float s10 = 0.f, s11 = 0.f, s12 = 0.f;
#pragma unroll
        for (int nf = 0; nf < 4; nf++) {
            const int n = n0 + wn * 32 + nf * 8 + (lane & 3) * 2;
            const float b1a = __ldg(&g_b1f[n]), b1b = __ldg(&g_b1f[n + 1]);
            const float wa0 = __ldg(&ex_w2[n * 3 + 0]);
            const float wa1 = __ldg(&ex_w2[n * 3 + 1]);
            const float wa2 = __ldg(&ex_w2[n * 3 + 2]);
            const float wb0 = __ldg(&ex_w2[n * 3 + 3]);
            const float wb1 = __ldg(&ex_w2[n * 3 + 4]);
            const float wb2 = __ldg(&ex_w2[n * 3 + 5]);
            const float v00 = gelu_exact(acc[mi][nf][0] + b1a);
            const float v01 = gelu_exact(acc[mi][nf][1] + b1b);
            const float v10 = gelu_exact(acc[mi][nf][2] + b1a);
            const float v11 = gelu_exact(acc[mi][nf][3] + b1b);
            s00 += v00 * wa0 + v01 * wb0;
            s01 += v00 * wa1 + v01 * wb1;
            s02 += v00 * wa2 + v01 * wb2;
            s10 += v10 * wa0 + v11 * wb0;
            s11 += v10 * wa1 + v11 * wb1;
            s12 += v10 * wa2 + v11 * wb2;
        }
#pragma unroll
        for (int o = 2; o; o >>= 1) {
            s00 += __shfl_xor_sync(0xffffffffu, s00, o);
            s01 += __shfl_xor_sync(0xffffffffu, s01, o);
            s02 += __shfl_xor_sync(0xffffffffu, s02, o);
            s10 += __shfl_xor_sync(0xffffffffu, s10, o);
            s11 += __shfl_xor_sync(0xffffffffu, s11, o);
            s12 += __shfl_xor_sync(0xffffffffu, s12, o);
        }
        if ((lane & 3) == 0) {
            const int rl = wm * 32 + mi * 16 + (lane >> 2);
            atomicAdd(&sred[rl * NC + 0], s00);
            atomicAdd(&sred[rl * NC + 1], s01);
            atomicAdd(&sred[rl * NC + 2], s02);
            atomicAdd(&sred[(rl + 8) * NC + 0], s10);
            atomicAdd(&sred[(rl + 8) * NC + 1], s11);
            atomicAdd(&sred[(rl + 8) * NC + 2], s12);
        }
    }
    __syncthreads();

    if (t < BM) {
        const int row = row0 + t;
        const float gw = g_gate[row * NE + e];
        atomicAdd(&out[row * NC + 0], gw * sred[t * NC + 0]);
        atomicAdd(&out[row * NC + 1], gw * sred[t * NC + 1]);
        atomicAdd(&out[row * NC + 2], gw * sred[t * NC + 2]);
    }
}

// ==================================================================================
extern "C" void kernel_launch(void* const* d_in, const int* in_sizes, int n_in,
                              void* d_out, int out_size)
{
    const float* x       = (const float*)d_in[0];
    const float* gln_g   = (const float*)d_in[1];
    const float* gln_b   = (const float*)d_in[2];
    const float* gate_w  = (const float*)d_in[3];
    const float* gate_b  = (const float*)d_in[4];
    const float* ex_ln_g = (const float*)d_in[5];
    const float* ex_ln_b = (const float*)d_in[6];
    const float* ex_w1   = (const float*)d_in[7];
    const float* ex_b1   = (const float*)d_in[8];
    const float* ex_w2   = (const float*)d_in[9];
    const float* ex_b2   = (const float*)d_in[10];
    float* out = (float*)d_out;

    cudaFuncSetAttribute(gemm_kernel, cudaFuncAttributeMaxDynamicSharedMemorySize, DYN_SMEM);

    ln_gate_kernel<<<B_TOK / 8, 256>>>(x, gln_g, gln_b, gate_w, gate_b, ex_b2, out);
    b1_init_kernel<<<NTOT / 256, 256>>>(ex_b1);
    fold_w1_kernel<<<dim3(HID / 32, DIM / 32, NE), dim3(32, 8)>>>(ex_w1, ex_ln_g, ex_ln_b);
    gemm_kernel<<<dim3(B_TOK / BM, NTOT / BN), 256, DYN_SMEM>>>(ex_w2, out);
}